// round 16
// baseline (speedup 1.0000x reference)
#include <cuda_runtime.h>
#include <math.h>
#include <stdint.h>

#define B_ 8
#define N_ 4096
#define C_ 256
#define K_ 32
#define M_ (B_*N_)

// Scratch
__device__ __align__(16) float g_feat[M_*C_];
__device__ __align__(16) float g_pos[M_*C_];

// ---- packed fp32x2 helpers (FFMA2 via PTX fma.rn.f32x2) ----
__device__ __forceinline__ unsigned long long pack2(float x) {
    unsigned long long r;
    asm("mov.b64 %0, {%1, %1};" : "=l"(r) : "f"(x));
    return r;
}
__device__ __forceinline__ void fma2(unsigned long long& d,
                                     unsigned long long a, unsigned long long b) {
    asm("fma.rn.f32x2 %0, %1, %2, %0;" : "+l"(d) : "l"(a), "l"(b));
}
__device__ __forceinline__ float2 unpack2(unsigned long long v) {
    float2 f;
    asm("mov.b64 {%0, %1}, %2;" : "=f"(f.x), "=f"(f.y) : "l"(v));
    return f;
}

// ---------------------------------------------------------------------------
// Kernel 1: feat_pos = x @ W^T + bias ; split into g_feat / g_pos  (R5 proven)
// ---------------------------------------------------------------------------
__global__ __launch_bounds__(256) void gemm_feat_pos(
    const float* __restrict__ x, const float* __restrict__ W,
    const float* __restrict__ bias)
{
    __shared__ float as[16][64];
    __shared__ float bs[16][64];
    const int tid = threadIdx.x;
    const int row0 = blockIdx.y * 64;
    const int d0   = blockIdx.x * 64;
    const int tx = tid & 15, ty = tid >> 4;
    const int lr = tid >> 2, lc = tid & 3;
    float acc[4][4] = {};
    for (int kt = 0; kt < C_; kt += 16) {
        float4 va = *(const float4*)&x[(row0 + lr) * C_ + kt + lc * 4];
        float4 vb = *(const float4*)&W[(d0 + lr) * C_ + kt + lc * 4];
        as[lc*4+0][lr]=va.x; as[lc*4+1][lr]=va.y; as[lc*4+2][lr]=va.z; as[lc*4+3][lr]=va.w;
        bs[lc*4+0][lr]=vb.x; bs[lc*4+1][lr]=vb.y; bs[lc*4+2][lr]=vb.z; bs[lc*4+3][lr]=vb.w;
        __syncthreads();
        #pragma unroll
        for (int kk = 0; kk < 16; kk++) {
            float4 a = *(const float4*)&as[kk][ty*4];
            float4 b = *(const float4*)&bs[kk][tx*4];
            float ar[4]={a.x,a.y,a.z,a.w}, br[4]={b.x,b.y,b.z,b.w};
            #pragma unroll
            for (int i=0;i<4;i++)
                #pragma unroll
                for (int j=0;j<4;j++) acc[i][j] += ar[i]*br[j];
        }
        __syncthreads();
    }
    #pragma unroll
    for (int i=0;i<4;i++) {
        int row = row0 + ty*4 + i;
        #pragma unroll
        for (int j=0;j<4;j++) {
            int d = d0 + tx*4 + j;
            float v = acc[i][j] + bias[d];
            if (d < C_) g_feat[row*C_ + d] = v;
            else        g_pos[row*C_ + d - C_] = v;
        }
    }
}

// ---------------------------------------------------------------------------
// Kernel 2: normalize pos rows in place. grid = M, block = 64  (R5 proven)
// ---------------------------------------------------------------------------
__global__ __launch_bounds__(64) void norm_pos()
{
    const int row = blockIdx.x;
    float* p = g_pos + (size_t)row * C_;
    const int t = threadIdx.x;
    float4 v = *(float4*)&p[t*4];
    float ss = v.x*v.x + v.y*v.y + v.z*v.z + v.w*v.w;
    #pragma unroll
    for (int o = 16; o; o >>= 1) ss += __shfl_xor_sync(0xFFFFFFFFu, ss, o);
    __shared__ float s2[2];
    if ((t & 31) == 0) s2[t >> 5] = ss;
    __syncthreads();
    float inv = 1.0f / fmaxf(sqrtf(s2[0] + s2[1]), 1e-12f);
    v.x*=inv; v.y*=inv; v.z*=inv; v.w*=inv;
    *(float4*)&p[t*4] = v;
}

// ---------------------------------------------------------------------------
// Kernel 3: fused sim GEMM (FFMA2, 8x8 microtile) + top-32 + softmax + gather
// 128 q-rows x 128-key tiles, 256 threads.  16-dim double-buffered stages
// (16 syncs/tile, half of R15), register prefetch 4x float4 per stage.
// smem float layout:
//   AB  [2][16][128]  q chunk (c-major)   off 0      len 4096
//   BB  [2][16][128]  key chunk           off 4096   len 4096
//   S   [128][65]     S half-tile         off 8192   len 8320
//   TV  [32][128]     top values          off 16512  len 4096
//   TI  u16[32][128]  top indices         off 20608  len 2048 (floats)
// total 22656 floats = 90624 B -> 2 blocks/SM, grid 256 = 1 wave
// ---------------------------------------------------------------------------
#define AB0   0
#define BB0   4096
#define SOFF  8192
#define TVOFF 16512
#define TIOFF 20608
#define SMEM_FLOATS 22656

__global__ __launch_bounds__(256, 2) void topk_attn(float* __restrict__ out)
{
    extern __shared__ float sm[];
    float* S  = sm + SOFF;
    float* tv = sm + TVOFF;
    uint16_t* ti = (uint16_t*)(sm + TIOFF);

    const int tid = threadIdx.x;
    const int w = tid >> 5, lane = tid & 31;
    const int batch = blockIdx.y;
    const int q0 = blockIdx.x * 128;
    const float* posb = g_pos + ((size_t)batch * N_ << 8);

    const int tx = tid & 15, ty = tid >> 4;      // 16x16 thread grid
    const int lrow = tid >> 1, seg = tid & 1;    // loader: 128 rows x 2 segs (8 dims each)

    // per-row top-k state (thread tid<128 owns q-row tid)
    int cnt = 0, thrp = 0;
    float thrv = 3.0e38f;

    for (int tile = 0; tile < 32; tile++) {
        const int kt0 = tile * 128;
        // acc2[i2][j]: rows (ty*8+2*i2, +1) x col (tx*8+j), packed f32x2
        unsigned long long acc2[4][8] = {};

        // prefetch stage 0: dims seg*8 .. seg*8+7
        const float* arow = &posb[((size_t)(q0 + lrow)) << 8];
        const float* brow0 = &posb[((size_t)(kt0 + lrow)) << 8];
        float4 pa0 = *(const float4*)&arow[seg*8];
        float4 pa1 = *(const float4*)&arow[seg*8 + 4];
        float4 pb0 = *(const float4*)&brow0[seg*8];
        float4 pb1 = *(const float4*)&brow0[seg*8 + 4];

        for (int st = 0; st < 16; st++) {
            const int buf = st & 1;
            // store prefetched regs -> smem (c-major)
            {
                float* A  = sm + AB0 + buf*2048;
                float* Bp = sm + BB0 + buf*2048;
                const int d0i = seg*8;
                A[(d0i+0)*128 + lrow] = pa0.x;
                A[(d0i+1)*128 + lrow] = pa0.y;
                A[(d0i+2)*128 + lrow] = pa0.z;
                A[(d0i+3)*128 + lrow] = pa0.w;
                A[(d0i+4)*128 + lrow] = pa1.x;
                A[(d0i+5)*128 + lrow] = pa1.y;
                A[(d0i+6)*128 + lrow] = pa1.z;
                A[(d0i+7)*128 + lrow] = pa1.w;
                Bp[(d0i+0)*128 + lrow] = pb0.x;
                Bp[(d0i+1)*128 + lrow] = pb0.y;
                Bp[(d0i+2)*128 + lrow] = pb0.z;
                Bp[(d0i+3)*128 + lrow] = pb0.w;
                Bp[(d0i+4)*128 + lrow] = pb1.x;
                Bp[(d0i+5)*128 + lrow] = pb1.y;
                Bp[(d0i+6)*128 + lrow] = pb1.z;
                Bp[(d0i+7)*128 + lrow] = pb1.w;
            }
            // prefetch next stage
            if (st + 1 < 16) {
                const int c0 = (st + 1) * 16 + seg*8;
                pa0 = *(const float4*)&arow[c0];
                pa1 = *(const float4*)&arow[c0 + 4];
                pb0 = *(const float4*)&brow0[c0];
                pb1 = *(const float4*)&brow0[c0 + 4];
            }
            __syncthreads();
            // compute 16 kk on this buffer (double-buffered, no trailing sync)
            const float* A  = sm + AB0 + buf*2048;
            const float* Bp = sm + BB0 + buf*2048;
            #pragma unroll
            for (int kk = 0; kk < 16; kk++) {
                ulonglong2 a01 = *(const ulonglong2*)&A[kk*128 + ty*8];     // rows 0..3
                ulonglong2 a23 = *(const ulonglong2*)&A[kk*128 + ty*8 + 4]; // rows 4..7
                float4 b0 = *(const float4*)&Bp[kk*128 + tx*8];
                float4 b1 = *(const float4*)&Bp[kk*128 + tx*8 + 4];
                unsigned long long ar[4] = {a01.x, a01.y, a23.x, a23.y};
                unsigned long long bp[8] = {pack2(b0.x), pack2(b0.y), pack2(b0.z), pack2(b0.w),
                                            pack2(b1.x), pack2(b1.y), pack2(b1.z), pack2(b1.w)};
                #pragma unroll
                for (int i2 = 0; i2 < 4; i2++)
                    #pragma unroll
                    for (int j = 0; j < 8; j++)
                        fma2(acc2[i2][j], ar[i2], bp[j]);
            }
        }
        __syncthreads();

        // dump + scan in two 64-col phases
        #pragma unroll
        for (int p = 0; p < 2; p++) {
            if ((tx >> 3) == p) {
                const int cb = (tx & 7) * 8;
                #pragma unroll
                for (int i2 = 0; i2 < 4; i2++) {
                    float* r0 = &S[(ty*8 + i2*2)*65 + cb];
                    float* r1 = &S[(ty*8 + i2*2 + 1)*65 + cb];
                    #pragma unroll
                    for (int j = 0; j < 8; j++) {
                        float2 f = unpack2(acc2[i2][j]);
                        r0[j] = f.x;
                        r1[j] = f.y;
                    }
                }
            }
            __syncthreads();
            if (tid < 128) {
                const int r = tid;
                const int kbase = kt0 + p*64;
                #pragma unroll 8
                for (int j = 0; j < 64; j++) {
                    float v = S[r*65 + j];
                    if (cnt < K_) {
                        tv[cnt*128 + r] = v; ti[cnt*128 + r] = (uint16_t)(kbase + j);
                        if (v < thrv) { thrv = v; thrp = cnt; }
                        cnt++;
                    } else if (v > thrv) {
                        tv[thrp*128 + r] = v; ti[thrp*128 + r] = (uint16_t)(kbase + j);
                        thrv = tv[r]; thrp = 0;
                        #pragma unroll
                        for (int i = 1; i < K_; i++) {
                            float t2 = tv[i*128 + r];
                            if (t2 < thrv) { thrv = t2; thrp = i; }
                        }
                    }
                }
            }
            __syncthreads();
        }
    }

    // softmax per row (order-invariant)
    if (tid < 128) {
        const int r = tid;
        float m = -3.0e38f;
        #pragma unroll
        for (int i = 0; i < K_; i++) m = fmaxf(m, tv[i*128 + r]);
        float s = 0.f;
        #pragma unroll
        for (int i = 0; i < K_; i++) { float e = expf(tv[i*128 + r] - m); tv[i*128 + r] = e; s += e; }
        float inv = 1.0f / s;
        #pragma unroll
        for (int i = 0; i < K_; i++) tv[i*128 + r] *= inv;
    }
    __syncthreads();

    // gather: 8 warps, 16 rows each, 8 floats/lane
    const float* fb = g_feat + ((size_t)batch * N_ << 8);
    for (int rr = w; rr < 128; rr += 8) {
        float a0[4] = {0.f,0.f,0.f,0.f}, a1[4] = {0.f,0.f,0.f,0.f};
        #pragma unroll 4
        for (int i = 0; i < K_; i++) {
            float wt = tv[i*128 + rr];
            const float* f = fb + ((size_t)ti[i*128 + rr] << 8) + lane*8;
            float4 u  = *(const float4*)f;
            float4 u2 = *(const float4*)(f + 4);
            a0[0]+=wt*u.x;  a0[1]+=wt*u.y;  a0[2]+=wt*u.z;  a0[3]+=wt*u.w;
            a1[0]+=wt*u2.x; a1[1]+=wt*u2.y; a1[2]+=wt*u2.z; a1[3]+=wt*u2.w;
        }
        float* o = out + (((size_t)batch * N_ + q0 + rr) << 8) + lane*8;
        *(float4*)o       = make_float4(a0[0],a0[1],a0[2],a0[3]);
        *(float4*)(o + 4) = make_float4(a1[0],a1[1],a1[2],a1[3]);
    }
}

// ---------------------------------------------------------------------------
extern "C" void kernel_launch(void* const* d_in, const int* in_sizes, int n_in,
                              void* d_out, int out_size)
{
    const float* x    = (const float*)d_in[0];
    const float* W    = (const float*)d_in[1];
    const float* bias = (const float*)d_in[2];
    float* out = (float*)d_out;

    gemm_feat_pos<<<dim3(512/64, M_/64), 256>>>(x, W, bias);
    norm_pos<<<M_, 64>>>();

    const int smem_bytes = SMEM_FLOATS * (int)sizeof(float);
    cudaFuncSetAttribute(topk_attn, cudaFuncAttributeMaxDynamicSharedMemorySize,
                         smem_bytes);
    topk_attn<<<dim3(N_/128, B_), 256, smem_bytes>>>(out);
}